// round 1
// baseline (speedup 1.0000x reference)
#include <cuda_runtime.h>

#define B_ 64
#define N_ 2048
#define H_ 512
#define D_ 512
#define A_ 512
#define M_ (B_*N_)
#define NEG_INF_ -1.0e9f

#define TM 128
#define TA 128
#define TK 16
#define SST 132   // padded smem row stride (floats); 132%4==0 keeps float4 alignment

// Scratch (no allocations allowed in kernel_launch)
__device__ float g_proj_h[B_*A_];
__device__ float g_scores[M_];

// ---------------------------------------------------------------------------
// Kernel A: proj_h[b,a] = dot(h[b,:], W_h[a,:])   (warp per output)
// ---------------------------------------------------------------------------
__global__ void proj_h_kernel(const float* __restrict__ h,
                              const float* __restrict__ Wh) {
    int gw   = blockIdx.x * 8 + (threadIdx.x >> 5);   // global warp id, 32768 total
    int lane = threadIdx.x & 31;
    int b = gw / A_;
    int a = gw % A_;
    const float* hr = h  + (size_t)b * H_;
    const float* wr = Wh + (size_t)a * H_;
    float s = 0.f;
    #pragma unroll 4
    for (int k = lane; k < H_; k += 32) s += hr[k] * wr[k];
    #pragma unroll
    for (int o = 16; o > 0; o >>= 1) s += __shfl_xor_sync(0xffffffffu, s, o);
    if (lane == 0) g_proj_h[(size_t)b * A_ + a] = s;
}

// ---------------------------------------------------------------------------
// Kernel B: fused scores
//   scores[m] = sum_a v[a] * tanh(proj_h[b,a] + sum_k enc[m,k]*We[a,k])
// 128x128 tile per block, 8x8 register microtile per thread, K-chunks of 16.
// All 128 rows of a block share one b (2048 % 128 == 0).
// ---------------------------------------------------------------------------
__global__ __launch_bounds__(256, 2)
void scores_kernel(const float* __restrict__ enc,
                   const float* __restrict__ We,
                   const float* __restrict__ v) {
    __shared__ float Es[TK * SST];
    __shared__ float Ws[TK * SST];
    __shared__ float vs[TA];
    __shared__ float ps[TA];
    __shared__ float red[TM * 17];

    const int tid = threadIdx.x;
    const int tx  = tid & 15;          // 0..15 -> column group
    const int ty  = tid >> 4;          // 0..15 -> row group
    const int m0  = blockIdx.x * TM;
    const int b   = m0 / N_;
    const float* Eb = enc + (size_t)m0 * D_;

    float sp[8];
    #pragma unroll
    for (int i = 0; i < 8; i++) sp[i] = 0.f;

    for (int a0 = 0; a0 < A_; a0 += TA) {
        __syncthreads();                       // protect vs/ps from prior epilogue readers
        if (tid < TA) {
            vs[tid] = v[a0 + tid];
            ps[tid] = g_proj_h[(size_t)b * A_ + a0 + tid];
        }

        float acc[8][8];
        #pragma unroll
        for (int i = 0; i < 8; i++)
            #pragma unroll
            for (int j = 0; j < 8; j++) acc[i][j] = 0.f;

        for (int k0 = 0; k0 < D_; k0 += TK) {
            __syncthreads();                   // protect Es/Ws before overwrite
            // Load E (128x16) and W (128x16) tiles, transposed into smem [k][row].
            #pragma unroll
            for (int it = 0; it < 2; it++) {
                int idx = tid + it * 256;      // 0..511
                int row = idx >> 2;            // 0..127
                int kv  = (idx & 3) * 4;       // 0,4,8,12
                float4 ev = *(const float4*)&Eb[(size_t)row * D_ + k0 + kv];
                Es[(kv + 0) * SST + row] = ev.x;
                Es[(kv + 1) * SST + row] = ev.y;
                Es[(kv + 2) * SST + row] = ev.z;
                Es[(kv + 3) * SST + row] = ev.w;
                float4 wv = *(const float4*)&We[(size_t)(a0 + row) * D_ + k0 + kv];
                Ws[(kv + 0) * SST + row] = wv.x;
                Ws[(kv + 1) * SST + row] = wv.y;
                Ws[(kv + 2) * SST + row] = wv.z;
                Ws[(kv + 3) * SST + row] = wv.w;
            }
            __syncthreads();

            #pragma unroll
            for (int kk = 0; kk < TK; kk++) {
                float4 ea = *(const float4*)&Es[kk * SST + ty * 8];
                float4 eb = *(const float4*)&Es[kk * SST + ty * 8 + 4];
                float4 wa = *(const float4*)&Ws[kk * SST + tx * 8];
                float4 wb = *(const float4*)&Ws[kk * SST + tx * 8 + 4];
                float ar[8] = {ea.x, ea.y, ea.z, ea.w, eb.x, eb.y, eb.z, eb.w};
                float br[8] = {wa.x, wa.y, wa.z, wa.w, wb.x, wb.y, wb.z, wb.w};
                #pragma unroll
                for (int i = 0; i < 8; i++)
                    #pragma unroll
                    for (int j = 0; j < 8; j++)
                        acc[i][j] += ar[i] * br[j];
            }
        }

        // Epilogue for this A-chunk: partial score contribution (tanh is
        // elementwise in a, so chunked accumulation is exact).
        #pragma unroll
        for (int i = 0; i < 8; i++) {
            float s = 0.f;
            #pragma unroll
            for (int j = 0; j < 8; j++) {
                int col = tx * 8 + j;
                s += vs[col] * tanhf(ps[col] + acc[i][j]);
            }
            sp[i] += s;
        }
    }

    // Reduce the 16 column-group partials per row.
    #pragma unroll
    for (int i = 0; i < 8; i++) red[(ty * 8 + i) * 17 + tx] = sp[i];
    __syncthreads();
    if (tid < TM) {
        float s = 0.f;
        #pragma unroll
        for (int j = 0; j < 16; j++) s += red[tid * 17 + j];
        g_scores[m0 + tid] = s;
    }
}

// ---------------------------------------------------------------------------
// Kernel C: masked softmax over N per batch -> alpha
// ---------------------------------------------------------------------------
__global__ void softmax_kernel(const int* __restrict__ mask,
                               float* __restrict__ alpha) {
    __shared__ float sred[256];
    const int b   = blockIdx.x;
    const int tid = threadIdx.x;
    const float* sc = g_scores + (size_t)b * N_;
    const int*   mk = mask     + (size_t)b * N_;

    float vals[8];
    float mx = -3.4e38f;
    #pragma unroll
    for (int i = 0; i < 8; i++) {
        int n = tid + i * 256;
        float s = (mk[n] == 0) ? NEG_INF_ : sc[n];
        vals[i] = s;
        mx = fmaxf(mx, s);
    }
    sred[tid] = mx;
    __syncthreads();
    #pragma unroll
    for (int o = 128; o > 0; o >>= 1) {
        if (tid < o) sred[tid] = fmaxf(sred[tid], sred[tid + o]);
        __syncthreads();
    }
    mx = sred[0];
    __syncthreads();

    float sum = 0.f;
    #pragma unroll
    for (int i = 0; i < 8; i++) {
        vals[i] = expf(vals[i] - mx);
        sum += vals[i];
    }
    sred[tid] = sum;
    __syncthreads();
    #pragma unroll
    for (int o = 128; o > 0; o >>= 1) {
        if (tid < o) sred[tid] += sred[tid + o];
        __syncthreads();
    }
    float inv = 1.f / sred[0];
    #pragma unroll
    for (int i = 0; i < 8; i++)
        alpha[(size_t)b * N_ + tid + i * 256] = vals[i] * inv;
}

// ---------------------------------------------------------------------------
// Kernel D: context[b,d] = sum_n alpha[b,n] * enc[b,n,d]
// grid (B, 4): 128 d-columns per block; 2 n-lanes per column.
// ---------------------------------------------------------------------------
__global__ void context_kernel(const float* __restrict__ enc,
                               const float* __restrict__ alpha,
                               float* __restrict__ ctx) {
    __shared__ float s[256];
    const int b   = blockIdx.x;
    const int d0  = blockIdx.y * 128;
    const int tid = threadIdx.x;
    const int d   = d0 + (tid & 127);
    const int nh  = tid >> 7;                 // 0 or 1
    const float* Eb = enc   + (size_t)b * N_ * D_;
    const float* al = alpha + (size_t)b * N_;

    float a0 = 0.f, a1 = 0.f, a2 = 0.f, a3 = 0.f;
    for (int n = nh; n < N_; n += 8) {
        a0 += al[n    ] * Eb[(size_t)(n    ) * D_ + d];
        a1 += al[n + 2] * Eb[(size_t)(n + 2) * D_ + d];
        a2 += al[n + 4] * Eb[(size_t)(n + 4) * D_ + d];
        a3 += al[n + 6] * Eb[(size_t)(n + 6) * D_ + d];
    }
    s[tid] = (a0 + a1) + (a2 + a3);
    __syncthreads();
    if (tid < 128) ctx[(size_t)b * D_ + d] = s[tid] + s[tid + 128];
}

// ---------------------------------------------------------------------------
extern "C" void kernel_launch(void* const* d_in, const int* in_sizes, int n_in,
                              void* d_out, int out_size) {
    const float* h    = (const float*)d_in[0];
    const float* enc  = (const float*)d_in[1];
    const int*   mask = (const int*)  d_in[2];
    const float* Wh   = (const float*)d_in[3];
    const float* We   = (const float*)d_in[4];
    const float* v    = (const float*)d_in[5];

    float* out   = (float*)d_out;
    float* ctx   = out;               // (B, D) first
    float* alpha = out + B_ * D_;     // (B, N) second

    proj_h_kernel <<<(B_ * A_) / 8, 256>>>(h, Wh);
    scores_kernel <<<M_ / TM,       256>>>(enc, We, v);
    softmax_kernel<<<B_,            256>>>(mask, alpha);
    context_kernel<<<dim3(B_, 4),   256>>>(enc, alpha, ctx);
}

// round 3
// speedup vs baseline: 2.2185x; 2.2185x over previous
#include <cuda_runtime.h>
#include <cuda_bf16.h>
#include <cstdint>

#define B_ 64
#define N_ 2048
#define H_ 512
#define D_ 512
#define A_ 512
#define M_ (B_*N_)
#define NEG_INF_ -1.0e9f

// ---------------- persistent device scratch ----------------
__device__ float g_proj_h[B_*A_];
__device__ float g_scores[M_];
__device__ __align__(16) __nv_bfloat16 g_We_hi[A_*D_];
__device__ __align__(16) __nv_bfloat16 g_We_lo[A_*D_];

__device__ __forceinline__ uint32_t smem_u32(const void* p) {
    uint32_t a;
    asm("{ .reg .u64 t; cvta.to.shared.u64 t, %1; cvt.u32.u64 %0, t; }" : "=r"(a) : "l"(p));
    return a;
}

#define LDSM_X4(r, addr)                                                          \
    asm volatile("ldmatrix.sync.aligned.m8n8.x4.shared.b16 {%0,%1,%2,%3}, [%4];"  \
        : "=r"((r)[0]), "=r"((r)[1]), "=r"((r)[2]), "=r"((r)[3]) : "r"(addr))

#define MMA_BF16(d, a, b0, b1)                                                    \
    asm volatile("mma.sync.aligned.m16n8k16.row.col.f32.bf16.bf16.f32 "           \
        "{%0,%1,%2,%3}, {%4,%5,%6,%7}, {%8,%9}, {%0,%1,%2,%3};"                   \
        : "+f"((d)[0]), "+f"((d)[1]), "+f"((d)[2]), "+f"((d)[3])                  \
        : "r"((a)[0]), "r"((a)[1]), "r"((a)[2]), "r"((a)[3]), "r"(b0), "r"(b1))

// smem layout (bytes). E tiles: 128 rows x stride 40 bf16 (80B). W: 256 x 40.
#define OFF_EHI 0
#define OFF_ELO 10240
#define OFF_WHI 20480
#define OFF_WLO 40960
#define OFF_VS  61440
#define OFF_PS  63488
#define OFF_RED 65536
#define SMEM_BYTES 67584

// ---------------------------------------------------------------------------
__global__ void proj_h_kernel(const float* __restrict__ h,
                              const float* __restrict__ Wh) {
    int gw   = blockIdx.x * 8 + (threadIdx.x >> 5);
    int lane = threadIdx.x & 31;
    int b = gw / A_, a = gw % A_;
    const float* hr = h  + (size_t)b * H_;
    const float* wr = Wh + (size_t)a * H_;
    float s = 0.f;
    #pragma unroll 4
    for (int k = lane; k < H_; k += 32) s += hr[k] * wr[k];
    #pragma unroll
    for (int o = 16; o > 0; o >>= 1) s += __shfl_xor_sync(0xffffffffu, s, o);
    if (lane == 0) g_proj_h[(size_t)b * A_ + a] = s;
}

__global__ void wsplit_kernel(const float* __restrict__ We) {
    int i = blockIdx.x * blockDim.x + threadIdx.x;
    float x = We[i];
    __nv_bfloat16 hh = __float2bfloat16(x);
    g_We_hi[i] = hh;
    g_We_lo[i] = __float2bfloat16(x - __bfloat162float(hh));
}

// ---------------------------------------------------------------------------
// scores: D[m,a] = sum_k enc[m,k]*We[a,k], fused tanh/v epilogue on registers.
// CTA: 128 M x 256 N(a-chunk) x K=512, bf16x3 via mma.sync m16n8k16.
// ---------------------------------------------------------------------------
__global__ __launch_bounds__(512, 1)
void scores_kernel(const float* __restrict__ enc, const float* __restrict__ v) {
    extern __shared__ char smem[];
    const uint32_t sb = smem_u32(smem);
    const int tid  = threadIdx.x;
    const int lane = tid & 31;
    const int w    = tid >> 5;
    const int wm   = w & 3;            // 0..3 -> 32-row band
    const int wn   = w >> 2;           // 0..3 -> 64-col band
    const int m0   = blockIdx.x * 128;
    const int b    = blockIdx.x >> 4;

    float* vs = (float*)(smem + OFF_VS);
    float* ps = (float*)(smem + OFF_PS);
    vs[tid] = v[tid];
    ps[tid] = g_proj_h[(size_t)b * A_ + tid];

    // ldmatrix base addresses (per-lane)
    const uint32_t eBaseHi = sb + OFF_EHI + (uint32_t)(wm * 32 + (lane & 15)) * 80 + (uint32_t)(lane >> 4) * 16;
    const uint32_t eBaseLo = eBaseHi + (OFF_ELO - OFF_EHI);
    const int q = lane >> 3;
    const uint32_t wBaseHi = sb + OFF_WHI + (uint32_t)(wn * 64 + ((q >> 1) << 3) + (lane & 7)) * 80 + (uint32_t)(q & 1) * 16;
    const uint32_t wBaseLo = wBaseHi + (OFF_WLO - OFF_WHI);

    float sp[4] = {0.f, 0.f, 0.f, 0.f};

    #pragma unroll 1
    for (int ac = 0; ac < 2; ac++) {
        const int a0 = ac * 256;
        float c[2][8][4];
        #pragma unroll
        for (int i = 0; i < 2; i++)
            #pragma unroll
            for (int j = 0; j < 8; j++)
                #pragma unroll
                for (int e = 0; e < 4; e++) c[i][j][e] = 0.f;

        // prefetch chunk 0
        float4 er[2];
        uint4  whr[2], wlr[2];
        #pragma unroll
        for (int i = 0; i < 2; i++) {
            int idx = tid + i * 512, row = idx >> 3, kq = (idx & 7) << 2;
            er[i] = *(const float4*)(enc + (size_t)(m0 + row) * D_ + kq);
        }
        #pragma unroll
        for (int i = 0; i < 2; i++) {
            int idx = tid + i * 512, row = idx >> 2, k8 = (idx & 3) << 3;
            whr[i] = *(const uint4*)(g_We_hi + (size_t)(a0 + row) * D_ + k8);
            wlr[i] = *(const uint4*)(g_We_lo + (size_t)(a0 + row) * D_ + k8);
        }

        #pragma unroll 1
        for (int kc = 0; kc < 16; kc++) {
            __syncthreads();   // prior compute done (and ps/vs visible on first pass)
            // store staged tiles
            #pragma unroll
            for (int i = 0; i < 2; i++) {
                int idx = tid + i * 512, row = idx >> 3, kq = (idx & 7) << 2;
                uint32_t byo = (uint32_t)row * 80 + (uint32_t)kq * 2;
                float4 e = er[i];
                __nv_bfloat16 hx = __float2bfloat16(e.x), hy = __float2bfloat16(e.y);
                __nv_bfloat16 hz = __float2bfloat16(e.z), hw = __float2bfloat16(e.w);
                uint32_t hi01 = (uint32_t)__bfloat16_as_ushort(hx) | ((uint32_t)__bfloat16_as_ushort(hy) << 16);
                uint32_t hi23 = (uint32_t)__bfloat16_as_ushort(hz) | ((uint32_t)__bfloat16_as_ushort(hw) << 16);
                float lx = e.x - __bfloat162float(hx), ly = e.y - __bfloat162float(hy);
                float lz = e.z - __bfloat162float(hz), lw = e.w - __bfloat162float(hw);
                uint32_t lo01, lo23;
                asm("cvt.rn.bf16x2.f32 %0, %1, %2;" : "=r"(lo01) : "f"(ly), "f"(lx));
                asm("cvt.rn.bf16x2.f32 %0, %1, %2;" : "=r"(lo23) : "f"(lw), "f"(lz));
                *(uint2*)(smem + OFF_EHI + byo) = make_uint2(hi01, hi23);
                *(uint2*)(smem + OFF_ELO + byo) = make_uint2(lo01, lo23);
            }
            #pragma unroll
            for (int i = 0; i < 2; i++) {
                int idx = tid + i * 512, row = idx >> 2, k8 = (idx & 3) << 3;
                uint32_t byo = (uint32_t)row * 80 + (uint32_t)k8 * 2;
                *(uint4*)(smem + OFF_WHI + byo) = whr[i];
                *(uint4*)(smem + OFF_WLO + byo) = wlr[i];
            }
            // prefetch next chunk
            if (kc < 15) {
                int k0 = (kc + 1) * 32;
                #pragma unroll
                for (int i = 0; i < 2; i++) {
                    int idx = tid + i * 512, row = idx >> 3, kq = (idx & 7) << 2;
                    er[i] = *(const float4*)(enc + (size_t)(m0 + row) * D_ + k0 + kq);
                }
                #pragma unroll
                for (int i = 0; i < 2; i++) {
                    int idx = tid + i * 512, row = idx >> 2, k8 = (idx & 3) << 3;
                    whr[i] = *(const uint4*)(g_We_hi + (size_t)(a0 + row) * D_ + k0 + k8);
                    wlr[i] = *(const uint4*)(g_We_lo + (size_t)(a0 + row) * D_ + k0 + k8);
                }
            }
            __syncthreads();

            // compute: 2 k-steps of 16
            #pragma unroll
            for (int s = 0; s < 2; s++) {
                uint32_t aHi[2][4], aLo[2][4];
                #pragma unroll
                for (int i = 0; i < 2; i++) {
                    LDSM_X4(aHi[i], eBaseHi + (uint32_t)i * 1280 + (uint32_t)s * 32);
                    LDSM_X4(aLo[i], eBaseLo + (uint32_t)i * 1280 + (uint32_t)s * 32);
                }
                #pragma unroll
                for (int g = 0; g < 4; g++) {
                    uint32_t bH[4], bL[4];
                    LDSM_X4(bH, wBaseHi + (uint32_t)g * 1280 + (uint32_t)s * 32);
                    LDSM_X4(bL, wBaseLo + (uint32_t)g * 1280 + (uint32_t)s * 32);
                    #pragma unroll
                    for (int i = 0; i < 2; i++) {
                        MMA_BF16(c[i][2*g],   aHi[i], bH[0], bH[1]);
                        MMA_BF16(c[i][2*g+1], aHi[i], bH[2], bH[3]);
                        MMA_BF16(c[i][2*g],   aLo[i], bH[0], bH[1]);
                        MMA_BF16(c[i][2*g+1], aLo[i], bH[2], bH[3]);
                        MMA_BF16(c[i][2*g],   aHi[i], bL[0], bL[1]);
                        MMA_BF16(c[i][2*g+1], aHi[i], bL[2], bL[3]);
                    }
                }
            }
        }

        // fused epilogue on register fragments
        #pragma unroll
        for (int i = 0; i < 2; i++)
            #pragma unroll
            for (int j = 0; j < 8; j++)
                #pragma unroll
                for (int e = 0; e < 4; e++) {
                    int col = a0 + wn * 64 + j * 8 + (lane & 3) * 2 + (e & 1);
                    float x  = ps[col] + c[i][j][e];
                    float ex = __expf(2.f * x);
                    float th = 1.f - __fdividef(2.f, ex + 1.f);
                    sp[i * 2 + (e >> 1)] += vs[col] * th;
                }
    }

    // cross-lane (cols) then cross-warp (wn) reduction
    #pragma unroll
    for (int slot = 0; slot < 4; slot++) {
        sp[slot] += __shfl_xor_sync(0xffffffffu, sp[slot], 1);
        sp[slot] += __shfl_xor_sync(0xffffffffu, sp[slot], 2);
    }
    float* red = (float*)(smem + OFF_RED);
    __syncthreads();
    if ((lane & 3) == 0) {
        #pragma unroll
        for (int slot = 0; slot < 4; slot++) {
            int row = wm * 32 + (slot >> 1) * 16 + (slot & 1) * 8 + (lane >> 2);
            red[row * 4 + wn] = sp[slot];
        }
    }
    __syncthreads();
    if (tid < 128)
        g_scores[m0 + tid] = red[tid*4+0] + red[tid*4+1] + red[tid*4+2] + red[tid*4+3];
}

// ---------------------------------------------------------------------------
__global__ void softmax_kernel(const int* __restrict__ mask,
                               float* __restrict__ alpha) {
    __shared__ float sred[256];
    const int b   = blockIdx.x;
    const int tid = threadIdx.x;
    const float* sc = g_scores + (size_t)b * N_;
    const int*   mk = mask     + (size_t)b * N_;

    float vals[8];
    float mx = -3.4e38f;
    #pragma unroll
    for (int i = 0; i < 8; i++) {
        int n = tid + i * 256;
        float s = (mk[n] == 0) ? NEG_INF_ : sc[n];
        vals[i] = s;
        mx = fmaxf(mx, s);
    }
    sred[tid] = mx;
    __syncthreads();
    #pragma unroll
    for (int o = 128; o > 0; o >>= 1) {
        if (tid < o) sred[tid] = fmaxf(sred[tid], sred[tid + o]);
        __syncthreads();
    }
    mx = sred[0];
    __syncthreads();

    float sum = 0.f;
    #pragma unroll
    for (int i = 0; i < 8; i++) { vals[i] = expf(vals[i] - mx); sum += vals[i]; }
    sred[tid] = sum;
    __syncthreads();
    #pragma unroll
    for (int o = 128; o > 0; o >>= 1) {
        if (tid < o) sred[tid] += sred[tid + o];
        __syncthreads();
    }
    float inv = 1.f / sred[0];
    #pragma unroll
    for (int i = 0; i < 8; i++)
        alpha[(size_t)b * N_ + tid + i * 256] = vals[i] * inv;
}

// ---------------------------------------------------------------------------
__global__ void context_kernel(const float* __restrict__ enc,
                               const float* __restrict__ alpha,
                               float* __restrict__ ctx) {
    __shared__ float  sal[N_];
    __shared__ float4 sred[256];
    const int b  = blockIdx.x;
    const int d0 = blockIdx.y * 128;
    const int t  = threadIdx.x;
    for (int n = t; n < N_; n += 256) sal[n] = alpha[(size_t)b * N_ + n];
    __syncthreads();

    const int dl = (t & 31) * 4;
    const int nl = t >> 5;
    const float* base = enc + (size_t)b * N_ * D_ + d0 + dl;
    float4 acc = make_float4(0.f, 0.f, 0.f, 0.f);
    #pragma unroll 4
    for (int n = nl; n < N_; n += 8) {
        float a  = sal[n];
        float4 e = *(const float4*)(base + (size_t)n * D_);
        acc.x += a * e.x; acc.y += a * e.y; acc.z += a * e.z; acc.w += a * e.w;
    }
    sred[t] = acc;
    __syncthreads();
    if (t < 32) {
        float4 r = sred[t];
        #pragma unroll
        for (int j = 1; j < 8; j++) {
            float4 o = sred[t + 32 * j];
            r.x += o.x; r.y += o.y; r.z += o.z; r.w += o.w;
        }
        *(float4*)(ctx + (size_t)b * D_ + d0 + t * 4) = r;
    }
}

// ---------------------------------------------------------------------------
extern "C" void kernel_launch(void* const* d_in, const int* in_sizes, int n_in,
                              void* d_out, int out_size) {
    const float* h    = (const float*)d_in[0];
    const float* enc  = (const float*)d_in[1];
    const int*   mask = (const int*)  d_in[2];
    const float* Wh   = (const float*)d_in[3];
    const float* We   = (const float*)d_in[4];
    const float* v    = (const float*)d_in[5];

    float* out   = (float*)d_out;
    float* ctx   = out;               // (B, D) first
    float* alpha = out + B_ * D_;     // (B, N) second

    cudaFuncSetAttribute(scores_kernel, cudaFuncAttributeMaxDynamicSharedMemorySize, SMEM_BYTES);

    proj_h_kernel <<<(B_ * A_) / 8, 256>>>(h, Wh);
    wsplit_kernel <<<512, 512>>>(We);
    scores_kernel <<<M_ / 128, 512, SMEM_BYTES>>>(enc, v);
    softmax_kernel<<<B_, 256>>>(mask, alpha);
    context_kernel<<<dim3(B_, 4), 256>>>(enc, alpha, ctx);
}